// round 9
// baseline (speedup 1.0000x reference)
#include <cuda_runtime.h>
#include <cuda_bf16.h>
#include <cstdint>
#include <math.h>

#define BB 64
#define LL 512
#define DD 768

// ---------------------------------------------------------------------------
// Scratch (device globals)
// ---------------------------------------------------------------------------
__device__ __nv_bfloat16 g_E_hi[(size_t)BB * LL * LL];  // exp(att) split hi
__device__ __nv_bfloat16 g_E_lo[(size_t)BB * LL * LL];  // exp(att) split lo
__device__ float g_invp[BB * LL];
__device__ float g_invq[BB * LL];
__device__ float g_rinv[BB * LL];
__device__ float g_cinv[BB * LL];

// ---------------------------------------------------------------------------
// Helpers
// ---------------------------------------------------------------------------
__device__ __forceinline__ uint32_t smem_u32(const void* p) {
    uint32_t a;
    asm("{ .reg .u64 t; cvta.to.shared.u64 t, %1; cvt.u32.u64 %0, t; }"
        : "=r"(a) : "l"(p));
    return a;
}
#define CP_ASYNC(dst, src) \
    asm volatile("cp.async.cg.shared.global [%0], [%1], 16;" :: "r"(dst), "l"(src))
#define CP_COMMIT() asm volatile("cp.async.commit_group;")
#define CP_WAIT1()  asm volatile("cp.async.wait_group 1;")
#define CP_WAIT0()  asm volatile("cp.async.wait_group 0;")

__device__ __forceinline__ void mma16816(float* c, const uint32_t* a, const uint32_t* b) {
    asm volatile("mma.sync.aligned.m16n8k16.row.col.f32.bf16.bf16.f32 "
                 "{%0,%1,%2,%3}, {%4,%5,%6,%7}, {%8,%9}, {%0,%1,%2,%3};"
                 : "+f"(c[0]), "+f"(c[1]), "+f"(c[2]), "+f"(c[3])
                 : "r"(a[0]), "r"(a[1]), "r"(a[2]), "r"(a[3]), "r"(b[0]), "r"(b[1]));
}
// split a float2 into packed bf16x2 hi and lo (x -> low 16 bits)
__device__ __forceinline__ void splitp(float2 v, uint32_t& hi, uint32_t& lo) {
    __nv_bfloat162 h = __floats2bfloat162_rn(v.x, v.y);
    hi = *(uint32_t*)&h;
    float hx = __bfloat162float(h.x);
    float hy = __bfloat162float(h.y);
    __nv_bfloat162 l = __floats2bfloat162_rn(v.x - hx, v.y - hy);
    lo = *(uint32_t*)&l;
}
// hi-only pack
__device__ __forceinline__ uint32_t packbf(float2 v) {
    __nv_bfloat162 h = __floats2bfloat162_rn(v.x, v.y);
    return *(uint32_t*)&h;
}

// ---------------------------------------------------------------------------
// inverse L2 norms (proven R1)
// ---------------------------------------------------------------------------
__global__ void norms_kernel(const float* __restrict__ p,
                             const float* __restrict__ q) {
    int warp = (blockIdx.x * blockDim.x + threadIdx.x) >> 5;
    int lane = threadIdx.x & 31;
    if (warp >= 2 * BB * LL) return;
    const float* src; float* dst; int r;
    if (warp < BB * LL) { src = p; dst = g_invp; r = warp; }
    else                { src = q; dst = g_invq; r = warp - BB * LL; }
    const float4* row = (const float4*)(src + (size_t)r * DD);
    float s = 0.f;
#pragma unroll
    for (int i = 0; i < DD / 128; i++) {
        float4 v = row[lane + i * 32];
        s += v.x * v.x + v.y * v.y + v.z * v.z + v.w * v.w;
    }
#pragma unroll
    for (int o = 16; o; o >>= 1) s += __shfl_xor_sync(0xffffffffu, s, o);
    if (lane == 0) dst[r] = 1.f / fmaxf(sqrtf(s), 1e-8f);
}

// ---------------------------------------------------------------------------
// HMMA att (hi-only bf16, proven R8): E = exp((p_i.q_j)*invp[i]*invq[j])
// NEW: epilogue stores E split to bf16 hi/lo (same bytes as fp32 before).
// ---------------------------------------------------------------------------
#define ATT_STG 18432
#define ATT_BOFF 12288

__global__ __launch_bounds__(256)
void att_hmma_kernel(const float* __restrict__ P, const float* __restrict__ Q) {
    __shared__ __align__(128) char smc[2 * ATT_STG];

    int b = blockIdx.z;
    int m0 = blockIdx.y * 128, n0 = blockIdx.x * 64;
    const float* A  = P + (size_t)b * LL * DD;
    const float* Bq = Q + (size_t)b * LL * DD;

    uint32_t sb = smem_u32(smc);
    int t = threadIdx.x, wid = t >> 5, lane = t & 31;
    int wm = (wid >> 1) * 32, wn = (wid & 1) * 32;
    int r4 = lane >> 2, c4 = lane & 3;

    float acc[2][4][4];
#pragma unroll
    for (int i = 0; i < 2; i++)
#pragma unroll
        for (int j = 0; j < 4; j++)
#pragma unroll
            for (int k = 0; k < 4; k++) acc[i][j][k] = 0.f;

    auto LOAD = [&](int st, int k0) {
        uint32_t base = sb + (uint32_t)st * ATT_STG;
#pragma unroll
        for (int u = 0; u < 2; u++) {
            int c = t * 2 + u, row = c >> 2, cc = c & 3;
            CP_ASYNC(base + row * 96 + cc * 16,
                     A + (size_t)(m0 + row) * DD + k0 + cc * 4);
        }
        {
            int row = t >> 2, cc = t & 3;
            CP_ASYNC(base + ATT_BOFF + row * 96 + cc * 16,
                     Bq + (size_t)(n0 + row) * DD + k0 + cc * 4);
        }
    };

    LOAD(0, 0);
    CP_COMMIT();

    const int NIT = DD / 16;   // 48
    for (int it = 0; it < NIT; it++) {
        if (it + 1 < NIT) { LOAD((it + 1) & 1, (it + 1) * 16); CP_COMMIT(); CP_WAIT1(); }
        else              { CP_WAIT0(); }
        __syncthreads();

        const float* At = (const float*)(smc + (it & 1) * ATT_STG);             // [128][24]
        const float* Bt = (const float*)(smc + (it & 1) * ATT_STG + ATT_BOFF);  // [64][24]

        uint32_t aHi[2][4], bHi[4][2];
#pragma unroll
        for (int i = 0; i < 2; i++) {
            int row0 = wm + i * 16 + r4;
            aHi[i][0] = packbf(*(const float2*)&At[row0 * 24 + 2 * c4]);
            aHi[i][1] = packbf(*(const float2*)&At[(row0 + 8) * 24 + 2 * c4]);
            aHi[i][2] = packbf(*(const float2*)&At[row0 * 24 + 2 * c4 + 8]);
            aHi[i][3] = packbf(*(const float2*)&At[(row0 + 8) * 24 + 2 * c4 + 8]);
        }
#pragma unroll
        for (int j = 0; j < 4; j++) {
            int n = wn + j * 8 + r4;
            bHi[j][0] = packbf(*(const float2*)&Bt[n * 24 + 2 * c4]);
            bHi[j][1] = packbf(*(const float2*)&Bt[n * 24 + 2 * c4 + 8]);
        }
#pragma unroll
        for (int i = 0; i < 2; i++)
#pragma unroll
            for (int j = 0; j < 4; j++)
                mma16816(acc[i][j], aHi[i], bHi[j]);
        __syncthreads();
    }

    // Epilogue: cosine scale + exp -> split store E_hi/E_lo
    const float* ip = g_invp + b * LL;
    const float* iq = g_invq + b * LL;
#pragma unroll
    for (int i = 0; i < 2; i++)
#pragma unroll
        for (int half = 0; half < 2; half++) {
            int gi = m0 + wm + i * 16 + r4 + half * 8;
            float rp = ip[gi];
            size_t base = ((size_t)b * LL + gi) * LL;
#pragma unroll
            for (int j = 0; j < 4; j++) {
                int col = n0 + wn + j * 8 + c4 * 2;
                float2 v;
                v.x = __expf(acc[i][j][half * 2 + 0] * rp * iq[col]);
                v.y = __expf(acc[i][j][half * 2 + 1] * rp * iq[col + 1]);
                uint32_t hv, lv;
                splitp(v, hv, lv);
                *(uint32_t*)(g_E_hi + base + col) = hv;
                *(uint32_t*)(g_E_lo + base + col) = lv;
            }
        }
}

// ---------------------------------------------------------------------------
// rowsum of E (hi+lo) -> g_rinv. One warp per row.
// ---------------------------------------------------------------------------
__global__ void rowsum_kernel() {
    int warp = (blockIdx.x * blockDim.x + threadIdx.x) >> 5;
    int lane = threadIdx.x & 31;
    if (warp >= BB * LL) return;
    const uint4* H = (const uint4*)(g_E_hi + (size_t)warp * LL);
    const uint4* L = (const uint4*)(g_E_lo + (size_t)warp * LL);
    float s = 0.f;
#pragma unroll
    for (int it = 0; it < 2; it++) {
        uint4 hv = H[lane + 32 * it];
        uint4 lv = L[lane + 32 * it];
        const __nv_bfloat162* hp = (const __nv_bfloat162*)&hv;
        const __nv_bfloat162* lp = (const __nv_bfloat162*)&lv;
#pragma unroll
        for (int k = 0; k < 4; k++) {
            float2 a = __bfloat1622float2(hp[k]);
            float2 c = __bfloat1622float2(lp[k]);
            s += a.x + a.y + c.x + c.y;
        }
    }
#pragma unroll
    for (int o = 16; o; o >>= 1) s += __shfl_xor_sync(0xffffffffu, s, o);
    if (lane == 0) g_rinv[warp] = 1.f / s;
}

// ---------------------------------------------------------------------------
// colsum of E (hi+lo) -> g_cinv. One block per batch, 2 cols per thread.
// ---------------------------------------------------------------------------
__global__ void colsum_kernel() {
    int b = blockIdx.x;
    int j2 = threadIdx.x;  // 256 threads
    const __nv_bfloat162* H = (const __nv_bfloat162*)(g_E_hi + (size_t)b * LL * LL);
    const __nv_bfloat162* L = (const __nv_bfloat162*)(g_E_lo + (size_t)b * LL * LL);
    float sx = 0.f, sy = 0.f;
#pragma unroll 8
    for (int i = 0; i < LL; i++) {
        float2 h = __bfloat1622float2(H[i * (LL / 2) + j2]);
        float2 l = __bfloat1622float2(L[i * (LL / 2) + j2]);
        sx += h.x + l.x;
        sy += h.y + l.y;
    }
    g_cinv[b * LL + 2 * j2 + 0] = 1.f / sx;
    g_cinv[b * LL + 2 * j2 + 1] = 1.f / sy;
}

// ---------------------------------------------------------------------------
// HMMA output GEMMs. A = E (bf16 hi/lo tiles, NO in-loop A-splits).
// B = fp32, in-loop split (3-MMA scheme kept).
// MODE 1 (out_p): C[m,n] = rinv[m] * sum_k E[m,k] * q[k,n]
// MODE 2 (out_q): C[m,n] = sum_k (E[m,k]*cinv[k]) * p[k,n]  (cinv on B frags)
// Stage: Ah@0 (6144B, pitch 48) Al@6144 B@12288 (16x68 fp32 = 4352) = 16640.
// ---------------------------------------------------------------------------
#define ST_B 12288
#define ST_SZ 16640
#define CINV_OFF 33280

template <int MODE>
__global__ __launch_bounds__(256)
void out_hmma_kernel(const float* __restrict__ V, float* __restrict__ Out) {
    __shared__ __align__(128) char smc[33536];   // 2*16640 + 2*64 cinv

    int b = blockIdx.z;
    int m0 = blockIdx.y * 128, n0 = blockIdx.x * 64;
    const __nv_bfloat16* Eh = g_E_hi + (size_t)b * LL * LL;
    const __nv_bfloat16* El = g_E_lo + (size_t)b * LL * LL;
    const float* Vb = V + (size_t)b * LL * DD;
    const float* cv = g_cinv + b * LL;

    uint32_t sb = smem_u32(smc);
    int t = threadIdx.x, wid = t >> 5, lane = t & 31;
    int wm = (wid >> 1) * 32, wn = (wid & 1) * 32;
    int r4 = lane >> 2, c4 = lane & 3;

    float acc[2][4][4];
#pragma unroll
    for (int i = 0; i < 2; i++)
#pragma unroll
        for (int j = 0; j < 4; j++)
#pragma unroll
            for (int k = 0; k < 4; k++) acc[i][j][k] = 0.f;

    int arow = t >> 1, acc_ = (t & 1);
    auto LOAD = [&](int st, int k0) {
        uint32_t base = sb + (uint32_t)st * ST_SZ;
        CP_ASYNC(base + arow * 48 + acc_ * 16,
                 Eh + (size_t)(m0 + arow) * LL + k0 + acc_ * 8);
        CP_ASYNC(base + 6144 + arow * 48 + acc_ * 16,
                 El + (size_t)(m0 + arow) * LL + k0 + acc_ * 8);
        {
            int row = t >> 4, cc = t & 15;
            CP_ASYNC(base + ST_B + row * 272 + cc * 16,
                     Vb + (size_t)(k0 + row) * DD + n0 + cc * 4);
        }
        if (MODE == 2 && t < 4)
            CP_ASYNC(sb + CINV_OFF + (uint32_t)st * 64 + t * 16, cv + k0 + t * 4);
    };

    LOAD(0, 0);
    CP_COMMIT();

    const int NIT = LL / 16;   // 32
    for (int it = 0; it < NIT; it++) {
        if (it + 1 < NIT) { LOAD((it + 1) & 1, (it + 1) * 16); CP_COMMIT(); CP_WAIT1(); }
        else              { CP_WAIT0(); }
        __syncthreads();

        const uint32_t* Ath = (const uint32_t*)(smc + (it & 1) * ST_SZ);  // pitch 12 words
        const uint32_t* Atl = Ath + 1536;                                 // +6144B
        const float* Bt = (const float*)(smc + (it & 1) * ST_SZ + ST_B);  // [16][68]

        float c0v = 1.f, c1v = 1.f, c8v = 1.f, c9v = 1.f;
        if (MODE == 2) {
            const float* Cs = (const float*)(smc + CINV_OFF + (it & 1) * 64);
            c0v = Cs[2 * c4];     c1v = Cs[2 * c4 + 1];
            c8v = Cs[2 * c4 + 8]; c9v = Cs[2 * c4 + 9];
        }

        uint32_t aHi[2][4], aLo[2][4], bHi[4][2], bLo[4][2];
#pragma unroll
        for (int i = 0; i < 2; i++) {
            int r0 = (wm + i * 16 + r4) * 12, r1 = r0 + 96;
            aHi[i][0] = Ath[r0 + c4];     aHi[i][1] = Ath[r1 + c4];
            aHi[i][2] = Ath[r0 + c4 + 4]; aHi[i][3] = Ath[r1 + c4 + 4];
            aLo[i][0] = Atl[r0 + c4];     aLo[i][1] = Atl[r1 + c4];
            aLo[i][2] = Atl[r0 + c4 + 4]; aLo[i][3] = Atl[r1 + c4 + 4];
        }
#pragma unroll
        for (int j = 0; j < 4; j++) {
            int n = wn + j * 8 + r4;
            float2 v0, v1;
            v0.x = Bt[(2 * c4) * 68 + n];
            v0.y = Bt[(2 * c4 + 1) * 68 + n];
            v1.x = Bt[(2 * c4 + 8) * 68 + n];
            v1.y = Bt[(2 * c4 + 9) * 68 + n];
            if (MODE == 2) {
                v0.x *= c0v; v0.y *= c1v;
                v1.x *= c8v; v1.y *= c9v;
            }
            splitp(v0, bHi[j][0], bLo[j][0]);
            splitp(v1, bHi[j][1], bLo[j][1]);
        }
#pragma unroll
        for (int i = 0; i < 2; i++)
#pragma unroll
            for (int j = 0; j < 4; j++) {
                mma16816(acc[i][j], aHi[i], bHi[j]);
                mma16816(acc[i][j], aLo[i], bHi[j]);
                mma16816(acc[i][j], aHi[i], bLo[j]);
            }
        __syncthreads();
    }

    // Epilogue
#pragma unroll
    for (int i = 0; i < 2; i++)
#pragma unroll
        for (int half = 0; half < 2; half++) {
            int gi = m0 + wm + i * 16 + r4 + half * 8;
            float rs = (MODE == 1) ? g_rinv[b * LL + gi] : 1.f;
            size_t base = ((size_t)b * LL + gi) * DD;
#pragma unroll
            for (int j = 0; j < 4; j++) {
                int col = n0 + wn + j * 8 + c4 * 2;
                float2 v;
                v.x = acc[i][j][half * 2 + 0] * rs;
                v.y = acc[i][j][half * 2 + 1] * rs;
                *(float2*)(Out + base + col) = v;
            }
        }
}

// ---------------------------------------------------------------------------
extern "C" void kernel_launch(void* const* d_in, const int* in_sizes, int n_in,
                              void* d_out, int out_size) {
    const float* p = (const float*)d_in[0];
    const float* q = (const float*)d_in[1];
    float* out = (float*)d_out;
    float* out_p = out;
    float* out_q = out + (size_t)BB * LL * DD;

    norms_kernel<<<(2 * BB * LL) / 8, 256>>>(p, q);

    att_hmma_kernel<<<dim3(LL / 64, LL / 128, BB), 256>>>(p, q);

    rowsum_kernel<<<(BB * LL) / 8, 256>>>();
    colsum_kernel<<<BB, 256>>>();

    out_hmma_kernel<1><<<dim3(DD / 64, LL / 128, BB), 256>>>(q, out_p);
    out_hmma_kernel<2><<<dim3(DD / 64, LL / 128, BB), 256>>>(p, out_q);
}

// round 10
// speedup vs baseline: 1.1639x; 1.1639x over previous
#include <cuda_runtime.h>
#include <cuda_bf16.h>
#include <cstdint>
#include <math.h>

#define BB 64
#define LL 512
#define DD 768

// ---------------------------------------------------------------------------
// Scratch (device globals)
// ---------------------------------------------------------------------------
__device__ __nv_bfloat16 g_E_hi[(size_t)BB * LL * LL];  // exp(att) split hi
__device__ __nv_bfloat16 g_E_lo[(size_t)BB * LL * LL];  // exp(att) split lo
__device__ float g_invp[BB * LL];
__device__ float g_invq[BB * LL];
__device__ float g_rsum[BB * LL];
__device__ float g_csum[BB * LL];
__device__ float g_rinv[BB * LL];
__device__ float g_cinv[BB * LL];

// ---------------------------------------------------------------------------
// Helpers
// ---------------------------------------------------------------------------
__device__ __forceinline__ uint32_t smem_u32(const void* p) {
    uint32_t a;
    asm("{ .reg .u64 t; cvta.to.shared.u64 t, %1; cvt.u32.u64 %0, t; }"
        : "=r"(a) : "l"(p));
    return a;
}
#define CP_ASYNC(dst, src) \
    asm volatile("cp.async.cg.shared.global [%0], [%1], 16;" :: "r"(dst), "l"(src))
#define CP_COMMIT() asm volatile("cp.async.commit_group;")
#define CP_WAIT1()  asm volatile("cp.async.wait_group 1;")
#define CP_WAIT0()  asm volatile("cp.async.wait_group 0;")

__device__ __forceinline__ void mma16816(float* c, const uint32_t* a, const uint32_t* b) {
    asm volatile("mma.sync.aligned.m16n8k16.row.col.f32.bf16.bf16.f32 "
                 "{%0,%1,%2,%3}, {%4,%5,%6,%7}, {%8,%9}, {%0,%1,%2,%3};"
                 : "+f"(c[0]), "+f"(c[1]), "+f"(c[2]), "+f"(c[3])
                 : "r"(a[0]), "r"(a[1]), "r"(a[2]), "r"(a[3]), "r"(b[0]), "r"(b[1]));
}
// split a float2 into packed bf16x2 hi and lo (x -> low 16 bits)
__device__ __forceinline__ void splitp(float2 v, uint32_t& hi, uint32_t& lo) {
    __nv_bfloat162 h = __floats2bfloat162_rn(v.x, v.y);
    hi = *(uint32_t*)&h;
    float hx = __bfloat162float(h.x);
    float hy = __bfloat162float(h.y);
    __nv_bfloat162 l = __floats2bfloat162_rn(v.x - hx, v.y - hy);
    lo = *(uint32_t*)&l;
}
// hi-only pack
__device__ __forceinline__ uint32_t packbf(float2 v) {
    __nv_bfloat162 h = __floats2bfloat162_rn(v.x, v.y);
    return *(uint32_t*)&h;
}

// ---------------------------------------------------------------------------
// zero the atomic accumulators (graph replays need fresh zeros every launch)
// ---------------------------------------------------------------------------
__global__ void zero_sums() {
    int i = blockIdx.x * blockDim.x + threadIdx.x;
    g_rsum[i] = 0.f;
    g_csum[i] = 0.f;
}

// ---------------------------------------------------------------------------
// invert sums -> rinv/cinv
// ---------------------------------------------------------------------------
__global__ void inv_sums() {
    int i = blockIdx.x * blockDim.x + threadIdx.x;
    g_rinv[i] = 1.f / g_rsum[i];
    g_cinv[i] = 1.f / g_csum[i];
}

// ---------------------------------------------------------------------------
// inverse L2 norms (proven R1)
// ---------------------------------------------------------------------------
__global__ void norms_kernel(const float* __restrict__ p,
                             const float* __restrict__ q) {
    int warp = (blockIdx.x * blockDim.x + threadIdx.x) >> 5;
    int lane = threadIdx.x & 31;
    if (warp >= 2 * BB * LL) return;
    const float* src; float* dst; int r;
    if (warp < BB * LL) { src = p; dst = g_invp; r = warp; }
    else                { src = q; dst = g_invq; r = warp - BB * LL; }
    const float4* row = (const float4*)(src + (size_t)r * DD);
    float s = 0.f;
#pragma unroll
    for (int i = 0; i < DD / 128; i++) {
        float4 v = row[lane + i * 32];
        s += v.x * v.x + v.y * v.y + v.z * v.z + v.w * v.w;
    }
#pragma unroll
    for (int o = 16; o; o >>= 1) s += __shfl_xor_sync(0xffffffffu, s, o);
    if (lane == 0) dst[r] = 1.f / fmaxf(sqrtf(s), 1e-8f);
}

// ---------------------------------------------------------------------------
// HMMA att (hi-only bf16, proven R8): E = exp((p_i.q_j)*invp[i]*invq[j])
// Epilogue: split store E_hi/E_lo + in-register row/col partial sums via
// warp shfl reductions + atomicAdd (replaces rowsum/colsum kernels).
// ---------------------------------------------------------------------------
#define ATT_STG 18432
#define ATT_BOFF 12288

__global__ __launch_bounds__(256)
void att_hmma_kernel(const float* __restrict__ P, const float* __restrict__ Q) {
    __shared__ __align__(128) char smc[2 * ATT_STG];

    int b = blockIdx.z;
    int m0 = blockIdx.y * 128, n0 = blockIdx.x * 64;
    const float* A  = P + (size_t)b * LL * DD;
    const float* Bq = Q + (size_t)b * LL * DD;

    uint32_t sb = smem_u32(smc);
    int t = threadIdx.x, wid = t >> 5, lane = t & 31;
    int wm = (wid >> 1) * 32, wn = (wid & 1) * 32;
    int r4 = lane >> 2, c4 = lane & 3;

    float acc[2][4][4];
#pragma unroll
    for (int i = 0; i < 2; i++)
#pragma unroll
        for (int j = 0; j < 4; j++)
#pragma unroll
            for (int k = 0; k < 4; k++) acc[i][j][k] = 0.f;

    auto LOAD = [&](int st, int k0) {
        uint32_t base = sb + (uint32_t)st * ATT_STG;
#pragma unroll
        for (int u = 0; u < 2; u++) {
            int c = t * 2 + u, row = c >> 2, cc = c & 3;
            CP_ASYNC(base + row * 96 + cc * 16,
                     A + (size_t)(m0 + row) * DD + k0 + cc * 4);
        }
        {
            int row = t >> 2, cc = t & 3;
            CP_ASYNC(base + ATT_BOFF + row * 96 + cc * 16,
                     Bq + (size_t)(n0 + row) * DD + k0 + cc * 4);
        }
    };

    LOAD(0, 0);
    CP_COMMIT();

    const int NIT = DD / 16;   // 48
    for (int it = 0; it < NIT; it++) {
        if (it + 1 < NIT) { LOAD((it + 1) & 1, (it + 1) * 16); CP_COMMIT(); CP_WAIT1(); }
        else              { CP_WAIT0(); }
        __syncthreads();

        const float* At = (const float*)(smc + (it & 1) * ATT_STG);             // [128][24]
        const float* Bt = (const float*)(smc + (it & 1) * ATT_STG + ATT_BOFF);  // [64][24]

        uint32_t aHi[2][4], bHi[4][2];
#pragma unroll
        for (int i = 0; i < 2; i++) {
            int row0 = wm + i * 16 + r4;
            aHi[i][0] = packbf(*(const float2*)&At[row0 * 24 + 2 * c4]);
            aHi[i][1] = packbf(*(const float2*)&At[(row0 + 8) * 24 + 2 * c4]);
            aHi[i][2] = packbf(*(const float2*)&At[row0 * 24 + 2 * c4 + 8]);
            aHi[i][3] = packbf(*(const float2*)&At[(row0 + 8) * 24 + 2 * c4 + 8]);
        }
#pragma unroll
        for (int j = 0; j < 4; j++) {
            int n = wn + j * 8 + r4;
            bHi[j][0] = packbf(*(const float2*)&Bt[n * 24 + 2 * c4]);
            bHi[j][1] = packbf(*(const float2*)&Bt[n * 24 + 2 * c4 + 8]);
        }
#pragma unroll
        for (int i = 0; i < 2; i++)
#pragma unroll
            for (int j = 0; j < 4; j++)
                mma16816(acc[i][j], aHi[i], bHi[j]);
        __syncthreads();
    }

    // Epilogue: cosine scale + exp (in place) -> split store E_hi/E_lo
    const float* ip = g_invp + b * LL;
    const float* iq = g_invq + b * LL;
#pragma unroll
    for (int i = 0; i < 2; i++)
#pragma unroll
        for (int half = 0; half < 2; half++) {
            int gi = m0 + wm + i * 16 + r4 + half * 8;
            float rp = ip[gi];
            size_t base = ((size_t)b * LL + gi) * LL;
#pragma unroll
            for (int j = 0; j < 4; j++) {
                int col = n0 + wn + j * 8 + c4 * 2;
                float2 v;
                v.x = __expf(acc[i][j][half * 2 + 0] * rp * iq[col]);
                v.y = __expf(acc[i][j][half * 2 + 1] * rp * iq[col + 1]);
                acc[i][j][half * 2 + 0] = v.x;
                acc[i][j][half * 2 + 1] = v.y;
                uint32_t hv, lv;
                splitp(v, hv, lv);
                *(uint32_t*)(g_E_hi + base + col) = hv;
                *(uint32_t*)(g_E_lo + base + col) = lv;
            }
        }

    // Row partial sums: each thread sums its 8 cols for each of its 4 rows;
    // shfl over the c4 quad (same row) -> one atomic per row per warp.
#pragma unroll
    for (int i = 0; i < 2; i++)
#pragma unroll
        for (int half = 0; half < 2; half++) {
            float s = 0.f;
#pragma unroll
            for (int j = 0; j < 4; j++)
                s += acc[i][j][half * 2 + 0] + acc[i][j][half * 2 + 1];
            s += __shfl_xor_sync(0xffffffffu, s, 1);
            s += __shfl_xor_sync(0xffffffffu, s, 2);
            if (c4 == 0) {
                int gi = m0 + wm + i * 16 + r4 + half * 8;
                atomicAdd(&g_rsum[b * LL + gi], s);
            }
        }

    // Col partial sums: each thread sums its 4 rows per col; shfl over r4
    // (same cols) -> 8 atomics for lanes with r4==0.
#pragma unroll
    for (int j = 0; j < 4; j++)
#pragma unroll
        for (int z = 0; z < 2; z++) {
            float s = acc[0][j][z] + acc[0][j][2 + z] + acc[1][j][z] + acc[1][j][2 + z];
            s += __shfl_xor_sync(0xffffffffu, s, 4);
            s += __shfl_xor_sync(0xffffffffu, s, 8);
            s += __shfl_xor_sync(0xffffffffu, s, 16);
            if (r4 == 0)
                atomicAdd(&g_csum[b * LL + n0 + wn + j * 8 + c4 * 2 + z], s);
        }
}

// ---------------------------------------------------------------------------
// FUSED output GEMMs: one kernel computes both
//   out_p[m,n] = rinv[m] * sum_k E[m,k] * q[k,n]
//   out_q[m,n] = sum_k (E[m,k]*cinv[k]) * p[k,n]
// A = E (bf16 hi/lo tiles, loaded once for both). B = q and p fp32, in-loop
// split. Stage: Ah@0 (6144,pitch 48) Al@6144 Bq@12288 (4352) Bp@16640 (4352)
// = 20992/stage; 2 stages + cinv = 42112 B static smem.
// ---------------------------------------------------------------------------
#define FO_BQ 12288
#define FO_BP 16640
#define FO_STG 20992
#define FO_CINV 41984

__global__ __launch_bounds__(256)
void out_fused_kernel(const float* __restrict__ Qv, const float* __restrict__ Pv,
                      float* __restrict__ OutP, float* __restrict__ OutQ) {
    __shared__ __align__(128) char smc[42112];

    int b = blockIdx.z;
    int m0 = blockIdx.y * 128, n0 = blockIdx.x * 64;
    const __nv_bfloat16* Eh = g_E_hi + (size_t)b * LL * LL;
    const __nv_bfloat16* El = g_E_lo + (size_t)b * LL * LL;
    const float* Qb = Qv + (size_t)b * LL * DD;
    const float* Pb = Pv + (size_t)b * LL * DD;
    const float* cv = g_cinv + b * LL;

    uint32_t sb = smem_u32(smc);
    int t = threadIdx.x, wid = t >> 5, lane = t & 31;
    int wm = (wid >> 1) * 32, wn = (wid & 1) * 32;
    int r4 = lane >> 2, c4 = lane & 3;

    float accP[2][4][4], accQ[2][4][4];
#pragma unroll
    for (int i = 0; i < 2; i++)
#pragma unroll
        for (int j = 0; j < 4; j++)
#pragma unroll
            for (int k = 0; k < 4; k++) { accP[i][j][k] = 0.f; accQ[i][j][k] = 0.f; }

    int arow = t >> 1, acc_ = (t & 1);
    int brow = t >> 4, bcc = t & 15;
    auto LOAD = [&](int st, int k0) {
        uint32_t base = sb + (uint32_t)st * FO_STG;
        CP_ASYNC(base + arow * 48 + acc_ * 16,
                 Eh + (size_t)(m0 + arow) * LL + k0 + acc_ * 8);
        CP_ASYNC(base + 6144 + arow * 48 + acc_ * 16,
                 El + (size_t)(m0 + arow) * LL + k0 + acc_ * 8);
        CP_ASYNC(base + FO_BQ + brow * 272 + bcc * 16,
                 Qb + (size_t)(k0 + brow) * DD + n0 + bcc * 4);
        CP_ASYNC(base + FO_BP + brow * 272 + bcc * 16,
                 Pb + (size_t)(k0 + brow) * DD + n0 + bcc * 4);
        if (t < 4)
            CP_ASYNC(sb + FO_CINV + (uint32_t)st * 64 + t * 16, cv + k0 + t * 4);
    };

    LOAD(0, 0);
    CP_COMMIT();

    const int NIT = LL / 16;   // 32
    for (int it = 0; it < NIT; it++) {
        if (it + 1 < NIT) { LOAD((it + 1) & 1, (it + 1) * 16); CP_COMMIT(); CP_WAIT1(); }
        else              { CP_WAIT0(); }
        __syncthreads();

        const uint32_t* Ath = (const uint32_t*)(smc + (it & 1) * FO_STG);  // pitch 12 words
        const uint32_t* Atl = Ath + 1536;                                  // +6144B
        const float* Btq = (const float*)(smc + (it & 1) * FO_STG + FO_BQ);  // [16][68]
        const float* Btp = (const float*)(smc + (it & 1) * FO_STG + FO_BP);  // [16][68]
        const float* Cs = (const float*)(smc + FO_CINV + (it & 1) * 64);

        float c0v = Cs[2 * c4],     c1v = Cs[2 * c4 + 1];
        float c8v = Cs[2 * c4 + 8], c9v = Cs[2 * c4 + 9];

        uint32_t aHi[2][4], aLo[2][4];
#pragma unroll
        for (int i = 0; i < 2; i++) {
            int r0 = (wm + i * 16 + r4) * 12, r1 = r0 + 96;
            aHi[i][0] = Ath[r0 + c4];     aHi[i][1] = Ath[r1 + c4];
            aHi[i][2] = Ath[r0 + c4 + 4]; aHi[i][3] = Ath[r1 + c4 + 4];
            aLo[i][0] = Atl[r0 + c4];     aLo[i][1] = Atl[r1 + c4];
            aLo[i][2] = Atl[r0 + c4 + 4]; aLo[i][3] = Atl[r1 + c4 + 4];
        }

        // ---- B = q -> accP ----
        {
            uint32_t bHi[4][2], bLo[4][2];
#pragma unroll
            for (int j = 0; j < 4; j++) {
                int n = wn + j * 8 + r4;
                float2 v0, v1;
                v0.x = Btq[(2 * c4) * 68 + n];
                v0.y = Btq[(2 * c4 + 1) * 68 + n];
                v1.x = Btq[(2 * c4 + 8) * 68 + n];
                v1.y = Btq[(2 * c4 + 9) * 68 + n];
                splitp(v0, bHi[j][0], bLo[j][0]);
                splitp(v1, bHi[j][1], bLo[j][1]);
            }
#pragma unroll
            for (int i = 0; i < 2; i++)
#pragma unroll
                for (int j = 0; j < 4; j++) {
                    mma16816(accP[i][j], aHi[i], bHi[j]);
                    mma16816(accP[i][j], aLo[i], bHi[j]);
                    mma16816(accP[i][j], aHi[i], bLo[j]);
                }
        }

        // ---- B = p * cinv[k] -> accQ ----
        {
            uint32_t bHi[4][2], bLo[4][2];
#pragma unroll
            for (int j = 0; j < 4; j++) {
                int n = wn + j * 8 + r4;
                float2 v0, v1;
                v0.x = Btp[(2 * c4) * 68 + n] * c0v;
                v0.y = Btp[(2 * c4 + 1) * 68 + n] * c1v;
                v1.x = Btp[(2 * c4 + 8) * 68 + n] * c8v;
                v1.y = Btp[(2 * c4 + 9) * 68 + n] * c9v;
                splitp(v0, bHi[j][0], bLo[j][0]);
                splitp(v1, bHi[j][1], bLo[j][1]);
            }
#pragma unroll
            for (int i = 0; i < 2; i++)
#pragma unroll
                for (int j = 0; j < 4; j++) {
                    mma16816(accQ[i][j], aHi[i], bHi[j]);
                    mma16816(accQ[i][j], aLo[i], bHi[j]);
                    mma16816(accQ[i][j], aHi[i], bLo[j]);
                }
        }
        __syncthreads();
    }

    // Epilogue: both outputs
#pragma unroll
    for (int i = 0; i < 2; i++)
#pragma unroll
        for (int half = 0; half < 2; half++) {
            int gi = m0 + wm + i * 16 + r4 + half * 8;
            float rs = g_rinv[b * LL + gi];
            size_t base = ((size_t)b * LL + gi) * DD;
#pragma unroll
            for (int j = 0; j < 4; j++) {
                int col = n0 + wn + j * 8 + c4 * 2;
                float2 vp, vq;
                vp.x = accP[i][j][half * 2 + 0] * rs;
                vp.y = accP[i][j][half * 2 + 1] * rs;
                vq.x = accQ[i][j][half * 2 + 0];
                vq.y = accQ[i][j][half * 2 + 1];
                *(float2*)(OutP + base + col) = vp;
                *(float2*)(OutQ + base + col) = vq;
            }
        }
}

// ---------------------------------------------------------------------------
extern "C" void kernel_launch(void* const* d_in, const int* in_sizes, int n_in,
                              void* d_out, int out_size) {
    const float* p = (const float*)d_in[0];
    const float* q = (const float*)d_in[1];
    float* out = (float*)d_out;
    float* out_p = out;
    float* out_q = out + (size_t)BB * LL * DD;

    zero_sums<<<(BB * LL) / 256, 256>>>();
    norms_kernel<<<(2 * BB * LL) / 8, 256>>>(p, q);

    att_hmma_kernel<<<dim3(LL / 64, LL / 128, BB), 256>>>(p, q);

    inv_sums<<<(BB * LL) / 256, 256>>>();

    out_fused_kernel<<<dim3(DD / 64, LL / 128, BB), 256>>>(q, p, out_p, out_q);
}

// round 11
// speedup vs baseline: 1.2856x; 1.1046x over previous
#include <cuda_runtime.h>
#include <cuda_bf16.h>
#include <cstdint>
#include <math.h>

#define BB 64
#define LL 512
#define DD 768

// ---------------------------------------------------------------------------
// Scratch (device globals)
// ---------------------------------------------------------------------------
__device__ __nv_bfloat16 g_ph[(size_t)BB * LL * DD];    // normalized p, bf16 hi
__device__ __nv_bfloat16 g_qh[(size_t)BB * LL * DD];    // normalized q, bf16 hi
__device__ __nv_bfloat16 g_E_hi[(size_t)BB * LL * LL];  // exp(att) split hi
__device__ __nv_bfloat16 g_E_lo[(size_t)BB * LL * LL];  // exp(att) split lo
__device__ float g_rsum[BB * LL];
__device__ float g_csum[BB * LL];
__device__ float g_rinv[BB * LL];
__device__ float g_cinv[BB * LL];

// ---------------------------------------------------------------------------
// Helpers
// ---------------------------------------------------------------------------
__device__ __forceinline__ uint32_t smem_u32(const void* p) {
    uint32_t a;
    asm("{ .reg .u64 t; cvta.to.shared.u64 t, %1; cvt.u32.u64 %0, t; }"
        : "=r"(a) : "l"(p));
    return a;
}
#define CP_ASYNC(dst, src) \
    asm volatile("cp.async.cg.shared.global [%0], [%1], 16;" :: "r"(dst), "l"(src))
#define CP_COMMIT() asm volatile("cp.async.commit_group;")
#define CP_WAIT1()  asm volatile("cp.async.wait_group 1;")
#define CP_WAIT2()  asm volatile("cp.async.wait_group 2;")
#define CP_WAIT0()  asm volatile("cp.async.wait_group 0;")

__device__ __forceinline__ void mma16816(float* c, const uint32_t* a, const uint32_t* b) {
    asm volatile("mma.sync.aligned.m16n8k16.row.col.f32.bf16.bf16.f32 "
                 "{%0,%1,%2,%3}, {%4,%5,%6,%7}, {%8,%9}, {%0,%1,%2,%3};"
                 : "+f"(c[0]), "+f"(c[1]), "+f"(c[2]), "+f"(c[3])
                 : "r"(a[0]), "r"(a[1]), "r"(a[2]), "r"(a[3]), "r"(b[0]), "r"(b[1]));
}
// split a float2 into packed bf16x2 hi and lo (x -> low 16 bits)
__device__ __forceinline__ void splitp(float2 v, uint32_t& hi, uint32_t& lo) {
    __nv_bfloat162 h = __floats2bfloat162_rn(v.x, v.y);
    hi = *(uint32_t*)&h;
    float hx = __bfloat162float(h.x);
    float hy = __bfloat162float(h.y);
    __nv_bfloat162 l = __floats2bfloat162_rn(v.x - hx, v.y - hy);
    lo = *(uint32_t*)&l;
}

// ---------------------------------------------------------------------------
// zero the atomic accumulators / invert them
// ---------------------------------------------------------------------------
__global__ void zero_sums() {
    int i = blockIdx.x * blockDim.x + threadIdx.x;
    g_rsum[i] = 0.f;
    g_csum[i] = 0.f;
}
__global__ void inv_sums() {
    int i = blockIdx.x * blockDim.x + threadIdx.x;
    g_rinv[i] = 1.f / g_rsum[i];
    g_cinv[i] = 1.f / g_csum[i];
}

// ---------------------------------------------------------------------------
// Fused: L2-normalize rows + convert to bf16 (hi only). One warp per row.
// ---------------------------------------------------------------------------
__global__ void normsplit_kernel(const float* __restrict__ p,
                                 const float* __restrict__ q) {
    int warp = (blockIdx.x * blockDim.x + threadIdx.x) >> 5;
    int lane = threadIdx.x & 31;
    if (warp >= 2 * BB * LL) return;
    const float* src; __nv_bfloat16* dst; int r;
    if (warp < BB * LL) { src = p; dst = g_ph; r = warp; }
    else                { src = q; dst = g_qh; r = warp - BB * LL; }
    const float4* row = (const float4*)(src + (size_t)r * DD);
    float4 v[6];
    float s = 0.f;
#pragma unroll
    for (int i = 0; i < 6; i++) {
        v[i] = row[lane + i * 32];
        s += v[i].x * v[i].x + v[i].y * v[i].y + v[i].z * v[i].z + v[i].w * v[i].w;
    }
#pragma unroll
    for (int o = 16; o; o >>= 1) s += __shfl_xor_sync(0xffffffffu, s, o);
    float inv = 1.f / fmaxf(sqrtf(s), 1e-8f);
    size_t base = (size_t)r * DD;
#pragma unroll
    for (int i = 0; i < 6; i++) {
        __nv_bfloat162 h0 = __floats2bfloat162_rn(v[i].x * inv, v[i].y * inv);
        __nv_bfloat162 h1 = __floats2bfloat162_rn(v[i].z * inv, v[i].w * inv);
        uint2 hv = make_uint2(*(uint32_t*)&h0, *(uint32_t*)&h1);
        *(uint2*)(dst + base + 4 * (lane + i * 32)) = hv;
    }
}

// ---------------------------------------------------------------------------
// HMMA att (bf16-hi operands): E = exp(phat . qhat^T)
// BM=128, BN=64, BK=32, 3-stage cp.async pipeline.
// Stage: A 128 rows x 80B pitch (64B data: 32 bf16) = 10240, B 64x80 = 5120
// -> 15360/stage, 3 stages = 46080 B static smem. Pitch 80B (20 words) is
// conflict-free for the 32-lane fragment LDS pattern.
// Epilogue: exp -> split store E_hi/E_lo + row/col atomics (proven R10).
// ---------------------------------------------------------------------------
#define ATT_STG 15360
#define ATT_BOFF 10240

__global__ __launch_bounds__(256)
void att_hmma_kernel() {
    __shared__ __align__(128) char smc[3 * ATT_STG];

    int b = blockIdx.z;
    int m0 = blockIdx.y * 128, n0 = blockIdx.x * 64;
    const __nv_bfloat16* Ph = g_ph + (size_t)b * LL * DD;
    const __nv_bfloat16* Qh = g_qh + (size_t)b * LL * DD;

    uint32_t sb = smem_u32(smc);
    int t = threadIdx.x, wid = t >> 5, lane = t & 31;
    int wm = (wid >> 1) * 32, wn = (wid & 1) * 32;
    int r4 = lane >> 2, c4 = lane & 3;

    float acc[2][4][4];
#pragma unroll
    for (int i = 0; i < 2; i++)
#pragma unroll
        for (int j = 0; j < 4; j++)
#pragma unroll
            for (int k = 0; k < 4; k++) acc[i][j][k] = 0.f;

    // A: 128 rows x 4 chunks(16B) = 512 -> 2/thread. B: 64 x 4 = 256 -> 1/thread.
    auto LOAD = [&](int st, int k0) {
        uint32_t base = sb + (uint32_t)st * ATT_STG;
#pragma unroll
        for (int u = 0; u < 2; u++) {
            int c = t * 2 + u, row = c >> 2, cc = c & 3;
            CP_ASYNC(base + row * 80 + cc * 16,
                     Ph + (size_t)(m0 + row) * DD + k0 + cc * 8);
        }
        {
            int row = t >> 2, cc = t & 3;
            CP_ASYNC(base + ATT_BOFF + row * 80 + cc * 16,
                     Qh + (size_t)(n0 + row) * DD + k0 + cc * 8);
        }
    };

    LOAD(0, 0);  CP_COMMIT();
    LOAD(1, 32); CP_COMMIT();

    const int NIT = DD / 32;   // 24
    for (int it = 0; it < NIT; it++) {
        if (it + 2 < NIT) LOAD((it + 2) % 3, (it + 2) * 32);
        CP_COMMIT();           // empty group near tail; keeps wait accounting simple
        CP_WAIT2();            // stage `it` guaranteed complete
        __syncthreads();

        const uint32_t* At = (const uint32_t*)(smc + (it % 3) * ATT_STG);  // pitch 20 words
        const uint32_t* Bt = At + 2560;                                    // +10240 B

#pragma unroll
        for (int s = 0; s < 2; s++) {          // two k16 steps per BK=32
            uint32_t aHi[2][4], bHi[4][2];
#pragma unroll
            for (int i = 0; i < 2; i++) {
                int r0 = (wm + i * 16 + r4) * 20;
                aHi[i][0] = At[r0 + 8 * s + c4];
                aHi[i][1] = At[r0 + 160 + 8 * s + c4];
                aHi[i][2] = At[r0 + 8 * s + c4 + 4];
                aHi[i][3] = At[r0 + 160 + 8 * s + c4 + 4];
            }
#pragma unroll
            for (int j = 0; j < 4; j++) {
                int n = (wn + j * 8 + r4) * 20;
                bHi[j][0] = Bt[n + 8 * s + c4];
                bHi[j][1] = Bt[n + 8 * s + c4 + 4];
            }
#pragma unroll
            for (int i = 0; i < 2; i++)
#pragma unroll
                for (int j = 0; j < 4; j++)
                    mma16816(acc[i][j], aHi[i], bHi[j]);
        }
        __syncthreads();
    }

    // Epilogue: exp (in place) -> split store E_hi/E_lo
#pragma unroll
    for (int i = 0; i < 2; i++)
#pragma unroll
        for (int half = 0; half < 2; half++) {
            int gi = m0 + wm + i * 16 + r4 + half * 8;
            size_t base = ((size_t)b * LL + gi) * LL;
#pragma unroll
            for (int j = 0; j < 4; j++) {
                int col = n0 + wn + j * 8 + c4 * 2;
                float2 v;
                v.x = __expf(acc[i][j][half * 2 + 0]);
                v.y = __expf(acc[i][j][half * 2 + 1]);
                acc[i][j][half * 2 + 0] = v.x;
                acc[i][j][half * 2 + 1] = v.y;
                uint32_t hv, lv;
                splitp(v, hv, lv);
                *(uint32_t*)(g_E_hi + base + col) = hv;
                *(uint32_t*)(g_E_lo + base + col) = lv;
            }
        }

    // Row partial sums (proven R10)
#pragma unroll
    for (int i = 0; i < 2; i++)
#pragma unroll
        for (int half = 0; half < 2; half++) {
            float s = 0.f;
#pragma unroll
            for (int j = 0; j < 4; j++)
                s += acc[i][j][half * 2 + 0] + acc[i][j][half * 2 + 1];
            s += __shfl_xor_sync(0xffffffffu, s, 1);
            s += __shfl_xor_sync(0xffffffffu, s, 2);
            if (c4 == 0) {
                int gi = m0 + wm + i * 16 + r4 + half * 8;
                atomicAdd(&g_rsum[b * LL + gi], s);
            }
        }

    // Col partial sums (proven R10)
#pragma unroll
    for (int j = 0; j < 4; j++)
#pragma unroll
        for (int z = 0; z < 2; z++) {
            float s = acc[0][j][z] + acc[0][j][2 + z] + acc[1][j][z] + acc[1][j][2 + z];
            s += __shfl_xor_sync(0xffffffffu, s, 4);
            s += __shfl_xor_sync(0xffffffffu, s, 8);
            s += __shfl_xor_sync(0xffffffffu, s, 16);
            if (r4 == 0)
                atomicAdd(&g_csum[b * LL + n0 + wn + j * 8 + c4 * 2 + z], s);
        }
}

// ---------------------------------------------------------------------------
// FUSED output GEMMs (proven R10, unchanged):
//   out_p[m,n] = rinv[m] * sum_k E[m,k] * q[k,n]
//   out_q[m,n] = sum_k (E[m,k]*cinv[k]) * p[k,n]
// ---------------------------------------------------------------------------
#define FO_BQ 12288
#define FO_BP 16640
#define FO_STG 20992
#define FO_CINV 41984

__global__ __launch_bounds__(256)
void out_fused_kernel(const float* __restrict__ Qv, const float* __restrict__ Pv,
                      float* __restrict__ OutP, float* __restrict__ OutQ) {
    __shared__ __align__(128) char smc[42112];

    int b = blockIdx.z;
    int m0 = blockIdx.y * 128, n0 = blockIdx.x * 64;
    const __nv_bfloat16* Eh = g_E_hi + (size_t)b * LL * LL;
    const __nv_bfloat16* El = g_E_lo + (size_t)b * LL * LL;
    const float* Qb = Qv + (size_t)b * LL * DD;
    const float* Pb = Pv + (size_t)b * LL * DD;
    const float* cv = g_cinv + b * LL;

    uint32_t sb = smem_u32(smc);
    int t = threadIdx.x, wid = t >> 5, lane = t & 31;
    int wm = (wid >> 1) * 32, wn = (wid & 1) * 32;
    int r4 = lane >> 2, c4 = lane & 3;

    float accP[2][4][4], accQ[2][4][4];
#pragma unroll
    for (int i = 0; i < 2; i++)
#pragma unroll
        for (int j = 0; j < 4; j++)
#pragma unroll
            for (int k = 0; k < 4; k++) { accP[i][j][k] = 0.f; accQ[i][j][k] = 0.f; }

    int arow = t >> 1, acc_ = (t & 1);
    int brow = t >> 4, bcc = t & 15;
    auto LOAD = [&](int st, int k0) {
        uint32_t base = sb + (uint32_t)st * FO_STG;
        CP_ASYNC(base + arow * 48 + acc_ * 16,
                 Eh + (size_t)(m0 + arow) * LL + k0 + acc_ * 8);
        CP_ASYNC(base + 6144 + arow * 48 + acc_ * 16,
                 El + (size_t)(m0 + arow) * LL + k0 + acc_ * 8);
        CP_ASYNC(base + FO_BQ + brow * 272 + bcc * 16,
                 Qb + (size_t)(k0 + brow) * DD + n0 + bcc * 4);
        CP_ASYNC(base + FO_BP + brow * 272 + bcc * 16,
                 Pb + (size_t)(k0 + brow) * DD + n0 + bcc * 4);
        if (t < 4)
            CP_ASYNC(sb + FO_CINV + (uint32_t)st * 64 + t * 16, cv + k0 + t * 4);
    };

    LOAD(0, 0);
    CP_COMMIT();

    const int NIT = LL / 16;   // 32
    for (int it = 0; it < NIT; it++) {
        if (it + 1 < NIT) { LOAD((it + 1) & 1, (it + 1) * 16); CP_COMMIT(); CP_WAIT1(); }
        else              { CP_WAIT0(); }
        __syncthreads();

        const uint32_t* Ath = (const uint32_t*)(smc + (it & 1) * FO_STG);  // pitch 12 words
        const uint32_t* Atl = Ath + 1536;                                  // +6144B
        const float* Btq = (const float*)(smc + (it & 1) * FO_STG + FO_BQ);  // [16][68]
        const float* Btp = (const float*)(smc + (it & 1) * FO_STG + FO_BP);  // [16][68]
        const float* Cs = (const float*)(smc + FO_CINV + (it & 1) * 64);

        float c0v = Cs[2 * c4],     c1v = Cs[2 * c4 + 1];
        float c8v = Cs[2 * c4 + 8], c9v = Cs[2 * c4 + 9];

        uint32_t aHi[2][4], aLo[2][4];
#pragma unroll
        for (int i = 0; i < 2; i++) {
            int r0 = (wm + i * 16 + r4) * 12, r1 = r0 + 96;
            aHi[i][0] = Ath[r0 + c4];     aHi[i][1] = Ath[r1 + c4];
            aHi[i][2] = Ath[r0 + c4 + 4]; aHi[i][3] = Ath[r1 + c4 + 4];
            aLo[i][0] = Atl[r0 + c4];     aLo[i][1] = Atl[r1 + c4];
            aLo[i][2] = Atl[r0 + c4 + 4]; aLo[i][3] = Atl[r1 + c4 + 4];
        }

        // ---- B = q -> accP ----
        {
            uint32_t bHi[4][2], bLo[4][2];
#pragma unroll
            for (int j = 0; j < 4; j++) {
                int n = wn + j * 8 + r4;
                float2 v0, v1;
                v0.x = Btq[(2 * c4) * 68 + n];
                v0.y = Btq[(2 * c4 + 1) * 68 + n];
                v1.x = Btq[(2 * c4 + 8) * 68 + n];
                v1.y = Btq[(2 * c4 + 9) * 68 + n];
                splitp(v0, bHi[j][0], bLo[j][0]);
                splitp(v1, bHi[j][1], bLo[j][1]);
            }
#pragma unroll
            for (int i = 0; i < 2; i++)
#pragma unroll
                for (int j = 0; j < 4; j++) {
                    mma16816(accP[i][j], aHi[i], bHi[j]);
                    mma16816(accP[i][j], aLo[i], bHi[j]);
                    mma16816(accP[i][j], aHi[i], bLo[j]);
                }
        }

        // ---- B = p * cinv[k] -> accQ ----
        {
            uint32_t bHi[4][2], bLo[4][2];
#pragma unroll
            for (int j = 0; j < 4; j++) {
                int n = wn + j * 8 + r4;
                float2 v0, v1;
                v0.x = Btp[(2 * c4) * 68 + n] * c0v;
                v0.y = Btp[(2 * c4 + 1) * 68 + n] * c1v;
                v1.x = Btp[(2 * c4 + 8) * 68 + n] * c8v;
                v1.y = Btp[(2 * c4 + 9) * 68 + n] * c9v;
                splitp(v0, bHi[j][0], bLo[j][0]);
                splitp(v1, bHi[j][1], bLo[j][1]);
            }
#pragma unroll
            for (int i = 0; i < 2; i++)
#pragma unroll
                for (int j = 0; j < 4; j++) {
                    mma16816(accQ[i][j], aHi[i], bHi[j]);
                    mma16816(accQ[i][j], aLo[i], bHi[j]);
                    mma16816(accQ[i][j], aHi[i], bLo[j]);
                }
        }
        __syncthreads();
    }

    // Epilogue: both outputs
#pragma unroll
    for (int i = 0; i < 2; i++)
#pragma unroll
        for (int half = 0; half < 2; half++) {
            int gi = m0 + wm + i * 16 + r4 + half * 8;
            float rs = g_rinv[b * LL + gi];
            size_t base = ((size_t)b * LL + gi) * DD;
#pragma unroll
            for (int j = 0; j < 4; j++) {
                int col = n0 + wn + j * 8 + c4 * 2;
                float2 vp, vq;
                vp.x = accP[i][j][half * 2 + 0] * rs;
                vp.y = accP[i][j][half * 2 + 1] * rs;
                vq.x = accQ[i][j][half * 2 + 0];
                vq.y = accQ[i][j][half * 2 + 1];
                *(float2*)(OutP + base + col) = vp;
                *(float2*)(OutQ + base + col) = vq;
            }
        }
}

// ---------------------------------------------------------------------------
extern "C" void kernel_launch(void* const* d_in, const int* in_sizes, int n_in,
                              void* d_out, int out_size) {
    const float* p = (const float*)d_in[0];
    const float* q = (const float*)d_in[1];
    float* out = (float*)d_out;
    float* out_p = out;
    float* out_q = out + (size_t)BB * LL * DD;

    zero_sums<<<(BB * LL) / 256, 256>>>();
    normsplit_kernel<<<(2 * BB * LL) / 8, 256>>>(p, q);

    att_hmma_kernel<<<dim3(LL / 64, LL / 128, BB), 256>>>();

    inv_sums<<<(BB * LL) / 256, 256>>>();

    out_fused_kernel<<<dim3(DD / 64, LL / 128, BB), 256>>>(q, p, out_p, out_q);
}

// round 14
// speedup vs baseline: 1.9955x; 1.5522x over previous
#include <cuda_runtime.h>
#include <cuda_fp16.h>
#include <cstdint>
#include <math.h>

#define BB 64
#define LL 512
#define DD 768

// ---------------------------------------------------------------------------
// Scratch (device globals)
// ---------------------------------------------------------------------------
__device__ __half g_ph[(size_t)BB * LL * DD];   // normalized p, fp16
__device__ __half g_qh[(size_t)BB * LL * DD];   // normalized q, fp16
__device__ __half g_pf[(size_t)BB * LL * DD];   // raw p, fp16
__device__ __half g_qf[(size_t)BB * LL * DD];   // raw q, fp16
__device__ __half g_Ef[(size_t)BB * LL * LL];   // exp(att), fp16
__device__ float g_rsum[BB * LL];
__device__ float g_csum[BB * LL];
__device__ float g_rinv[BB * LL];
__device__ float g_cinv[BB * LL];

// ---------------------------------------------------------------------------
// Helpers
// ---------------------------------------------------------------------------
__device__ __forceinline__ uint32_t smem_u32(const void* p) {
    uint32_t a;
    asm("{ .reg .u64 t; cvta.to.shared.u64 t, %1; cvt.u32.u64 %0, t; }"
        : "=r"(a) : "l"(p));
    return a;
}
#define CP_ASYNC(dst, src) \
    asm volatile("cp.async.cg.shared.global [%0], [%1], 16;" :: "r"(dst), "l"(src))
#define CP_COMMIT() asm volatile("cp.async.commit_group;")
#define CP_WAIT2()  asm volatile("cp.async.wait_group 2;")

__device__ __forceinline__ void mma16816f(float* c, const uint32_t* a, const uint32_t* b) {
    asm volatile("mma.sync.aligned.m16n8k16.row.col.f32.f16.f16.f32 "
                 "{%0,%1,%2,%3}, {%4,%5,%6,%7}, {%8,%9}, {%0,%1,%2,%3};"
                 : "+f"(c[0]), "+f"(c[1]), "+f"(c[2]), "+f"(c[3])
                 : "r"(a[0]), "r"(a[1]), "r"(a[2]), "r"(a[3]), "r"(b[0]), "r"(b[1]));
}
__device__ __forceinline__ uint32_t packh2(float x, float y) {
    __half2 h = __floats2half2_rn(x, y);
    return *(uint32_t*)&h;
}
__device__ __forceinline__ uint32_t packhh(__half a, __half b) {
    __half2 h = __halves2half2(a, b);
    return *(uint32_t*)&h;
}

// ---------------------------------------------------------------------------
// zero the atomic accumulators / invert them
// ---------------------------------------------------------------------------
__global__ void zero_sums() {
    int i = blockIdx.x * blockDim.x + threadIdx.x;
    g_rsum[i] = 0.f;
    g_csum[i] = 0.f;
}
__global__ void inv_sums() {
    int i = blockIdx.x * blockDim.x + threadIdx.x;
    g_rinv[i] = 1.f / g_rsum[i];
    g_cinv[i] = 1.f / g_csum[i];
}

// ---------------------------------------------------------------------------
// Fused: L2-normalize rows -> fp16 normalized + fp16 raw copies. 1 warp/row.
// ---------------------------------------------------------------------------
__global__ void normsplit_kernel(const float* __restrict__ p,
                                 const float* __restrict__ q) {
    int warp = (blockIdx.x * blockDim.x + threadIdx.x) >> 5;
    int lane = threadIdx.x & 31;
    if (warp >= 2 * BB * LL) return;
    const float* src; __half *dstn, *dstr; int r;
    if (warp < BB * LL) { src = p; dstn = g_ph; dstr = g_pf; r = warp; }
    else                { src = q; dstn = g_qh; dstr = g_qf; r = warp - BB * LL; }
    const float4* row = (const float4*)(src + (size_t)r * DD);
    float4 v[6];
    float s = 0.f;
#pragma unroll
    for (int i = 0; i < 6; i++) {
        v[i] = row[lane + i * 32];
        s += v[i].x * v[i].x + v[i].y * v[i].y + v[i].z * v[i].z + v[i].w * v[i].w;
    }
#pragma unroll
    for (int o = 16; o; o >>= 1) s += __shfl_xor_sync(0xffffffffu, s, o);
    float inv = 1.f / fmaxf(sqrtf(s), 1e-8f);
    size_t base = (size_t)r * DD;
#pragma unroll
    for (int i = 0; i < 6; i++) {
        size_t e = base + 4 * (lane + i * 32);
        uint2 hn = make_uint2(packh2(v[i].x * inv, v[i].y * inv),
                              packh2(v[i].z * inv, v[i].w * inv));
        uint2 hr = make_uint2(packh2(v[i].x, v[i].y),
                              packh2(v[i].z, v[i].w));
        *(uint2*)(dstn + e) = hn;
        *(uint2*)(dstr + e) = hr;
    }
}

// ---------------------------------------------------------------------------
// HMMA att (fp16 operands): E = exp(phat . qhat^T)
// BM=128, BN=64, BK=32, 3-stage cp.async pipeline (proven R11 structure).
// Epilogue: exp -> fp16 store + row/col atomics from the ROUNDED values.
// ---------------------------------------------------------------------------
#define ATT_STG 15360
#define ATT_BOFF 10240

__global__ __launch_bounds__(256)
void att_hmma_kernel() {
    __shared__ __align__(128) char smc[3 * ATT_STG];

    int b = blockIdx.z;
    int m0 = blockIdx.y * 128, n0 = blockIdx.x * 64;
    const __half* Ph = g_ph + (size_t)b * LL * DD;
    const __half* Qh = g_qh + (size_t)b * LL * DD;

    uint32_t sb = smem_u32(smc);
    int t = threadIdx.x, wid = t >> 5, lane = t & 31;
    int wm = (wid >> 1) * 32, wn = (wid & 1) * 32;
    int r4 = lane >> 2, c4 = lane & 3;

    float acc[2][4][4];
#pragma unroll
    for (int i = 0; i < 2; i++)
#pragma unroll
        for (int j = 0; j < 4; j++)
#pragma unroll
            for (int k = 0; k < 4; k++) acc[i][j][k] = 0.f;

    auto LOAD = [&](int st, int k0) {
        uint32_t base = sb + (uint32_t)st * ATT_STG;
#pragma unroll
        for (int u = 0; u < 2; u++) {
            int c = t * 2 + u, row = c >> 2, cc = c & 3;
            CP_ASYNC(base + row * 80 + cc * 16,
                     Ph + (size_t)(m0 + row) * DD + k0 + cc * 8);
        }
        {
            int row = t >> 2, cc = t & 3;
            CP_ASYNC(base + ATT_BOFF + row * 80 + cc * 16,
                     Qh + (size_t)(n0 + row) * DD + k0 + cc * 8);
        }
    };

    LOAD(0, 0);  CP_COMMIT();
    LOAD(1, 32); CP_COMMIT();

    const int NIT = DD / 32;   // 24
    for (int it = 0; it < NIT; it++) {
        if (it + 2 < NIT) LOAD((it + 2) % 3, (it + 2) * 32);
        CP_COMMIT();
        CP_WAIT2();
        __syncthreads();

        const uint32_t* At = (const uint32_t*)(smc + (it % 3) * ATT_STG);  // pitch 20 words
        const uint32_t* Bt = At + 2560;

#pragma unroll
        for (int s = 0; s < 2; s++) {
            uint32_t aHi[2][4], bHi[4][2];
#pragma unroll
            for (int i = 0; i < 2; i++) {
                int r0 = (wm + i * 16 + r4) * 20;
                aHi[i][0] = At[r0 + 8 * s + c4];
                aHi[i][1] = At[r0 + 160 + 8 * s + c4];
                aHi[i][2] = At[r0 + 8 * s + c4 + 4];
                aHi[i][3] = At[r0 + 160 + 8 * s + c4 + 4];
            }
#pragma unroll
            for (int j = 0; j < 4; j++) {
                int n = (wn + j * 8 + r4) * 20;
                bHi[j][0] = Bt[n + 8 * s + c4];
                bHi[j][1] = Bt[n + 8 * s + c4 + 4];
            }
#pragma unroll
            for (int i = 0; i < 2; i++)
#pragma unroll
                for (int j = 0; j < 4; j++)
                    mma16816f(acc[i][j], aHi[i], bHi[j]);
        }
        __syncthreads();
    }

    // Epilogue: exp -> fp16 store; sums from the rounded values
#pragma unroll
    for (int i = 0; i < 2; i++)
#pragma unroll
        for (int half = 0; half < 2; half++) {
            int gi = m0 + wm + i * 16 + r4 + half * 8;
            size_t base = ((size_t)b * LL + gi) * LL;
#pragma unroll
            for (int j = 0; j < 4; j++) {
                int col = n0 + wn + j * 8 + c4 * 2;
                __half2 h = __floats2half2_rn(__expf(acc[i][j][half * 2 + 0]),
                                              __expf(acc[i][j][half * 2 + 1]));
                *(uint32_t*)(g_Ef + base + col) = *(uint32_t*)&h;
                float2 hv = __half22float2(h);
                acc[i][j][half * 2 + 0] = hv.x;
                acc[i][j][half * 2 + 1] = hv.y;
            }
        }

    // Row partial sums (proven R10)
#pragma unroll
    for (int i = 0; i < 2; i++)
#pragma unroll
        for (int half = 0; half < 2; half++) {
            float s = 0.f;
#pragma unroll
            for (int j = 0; j < 4; j++)
                s += acc[i][j][half * 2 + 0] + acc[i][j][half * 2 + 1];
            s += __shfl_xor_sync(0xffffffffu, s, 1);
            s += __shfl_xor_sync(0xffffffffu, s, 2);
            if (c4 == 0) {
                int gi = m0 + wm + i * 16 + r4 + half * 8;
                atomicAdd(&g_rsum[b * LL + gi], s);
            }
        }

    // Col partial sums (proven R10)
#pragma unroll
    for (int j = 0; j < 4; j++)
#pragma unroll
        for (int z = 0; z < 2; z++) {
            float s = acc[0][j][z] + acc[0][j][2 + z] + acc[1][j][z] + acc[1][j][2 + z];
            s += __shfl_xor_sync(0xffffffffu, s, 4);
            s += __shfl_xor_sync(0xffffffffu, s, 8);
            s += __shfl_xor_sync(0xffffffffu, s, 16);
            if (r4 == 0)
                atomicAdd(&g_csum[b * LL + n0 + wn + j * 8 + c4 * 2 + z], s);
        }
}

// ---------------------------------------------------------------------------
// FUSED output GEMMs, all-fp16 operands (no splits):
//   out_p[m,n] = rinv[m] * sum_k E[m,k] * q[k,n]
//   out_q[m,n] = sum_k (E[m,k]*cinv[k]) * p[k,n]
// BM=128, BN=64, BK=16, 3-stage pipeline.
// Stage: E 128x48B = 6144, Bq 16x144B = 2304 @6144, Bp 2304 @8448 -> 10752.
// B-tile rows are 64 fp16 = 128B = 8 chunks: Bq covered by t<128
// ((t&127)>>3 rows, (t&127)&7 chunks), Bp by t>=128. cinv on t in [128,132).
// ---------------------------------------------------------------------------
#define FO_BQ 6144
#define FO_BP 8448
#define FO_STG 10752
#define FO_CINV 32256

__global__ __launch_bounds__(256)
void out_fused_kernel(float* __restrict__ OutP, float* __restrict__ OutQ) {
    __shared__ __align__(128) char smc[32448];

    int b = blockIdx.z;
    int m0 = blockIdx.y * 128, n0 = blockIdx.x * 64;
    const __half* Ef = g_Ef + (size_t)b * LL * LL;
    const __half* Qb = g_qf + (size_t)b * LL * DD;
    const __half* Pb = g_pf + (size_t)b * LL * DD;
    const float* cv = g_cinv + b * LL;

    uint32_t sb = smem_u32(smc);
    int t = threadIdx.x, wid = t >> 5, lane = t & 31;
    int wm = (wid >> 1) * 32, wn = (wid & 1) * 32;
    int r4 = lane >> 2, c4 = lane & 3;

    float accP[2][4][4], accQ[2][4][4];
#pragma unroll
    for (int i = 0; i < 2; i++)
#pragma unroll
        for (int j = 0; j < 4; j++)
#pragma unroll
            for (int k = 0; k < 4; k++) { accP[i][j][k] = 0.f; accQ[i][j][k] = 0.f; }

    // E: 128 rows x 2 chunks = 256 -> 1/thread.
    // Bq/Bp: 16 rows x 8 chunks = 128 each -> Bq on t<128, Bp on t>=128.
    int arow = t >> 1, acc_ = (t & 1);
    int brow = (t & 127) >> 3, bcc = (t & 127) & 7;
    auto LOAD = [&](int st, int k0) {
        uint32_t base = sb + (uint32_t)st * FO_STG;
        CP_ASYNC(base + arow * 48 + acc_ * 16,
                 Ef + (size_t)(m0 + arow) * LL + k0 + acc_ * 8);
        if (t < 128) {
            CP_ASYNC(base + FO_BQ + brow * 144 + bcc * 16,
                     Qb + (size_t)(k0 + brow) * DD + n0 + bcc * 8);
        } else {
            CP_ASYNC(base + FO_BP + brow * 144 + bcc * 16,
                     Pb + (size_t)(k0 + brow) * DD + n0 + bcc * 8);
            if (t < 132)
                CP_ASYNC(sb + FO_CINV + (uint32_t)st * 64 + (t - 128) * 16,
                         cv + k0 + (t - 128) * 4);
        }
    };

    LOAD(0, 0);  CP_COMMIT();
    LOAD(1, 16); CP_COMMIT();

    const int NIT = LL / 16;   // 32
    for (int it = 0; it < NIT; it++) {
        if (it + 2 < NIT) LOAD((it + 2) % 3, (it + 2) * 16);
        CP_COMMIT();
        CP_WAIT2();
        __syncthreads();

        const uint32_t* At = (const uint32_t*)(smc + (it % 3) * FO_STG);   // pitch 12 words
        const __half* Btq = (const __half*)(smc + (it % 3) * FO_STG + FO_BQ);  // [16][72]
        const __half* Btp = (const __half*)(smc + (it % 3) * FO_STG + FO_BP);  // [16][72]
        const float* Cs = (const float*)(smc + FO_CINV + (it % 3) * 64);

        float c0v = Cs[2 * c4],     c1v = Cs[2 * c4 + 1];
        float c8v = Cs[2 * c4 + 8], c9v = Cs[2 * c4 + 9];

        uint32_t aE[2][4];
#pragma unroll
        for (int i = 0; i < 2; i++) {
            int r0 = (wm + i * 16 + r4) * 12, r1 = r0 + 96;
            aE[i][0] = At[r0 + c4];     aE[i][1] = At[r1 + c4];
            aE[i][2] = At[r0 + c4 + 4]; aE[i][3] = At[r1 + c4 + 4];
        }

        uint32_t bq[4][2], bp[4][2];
#pragma unroll
        for (int j = 0; j < 4; j++) {
            int n = wn + j * 8 + r4;
            bq[j][0] = packhh(Btq[(2 * c4) * 72 + n],     Btq[(2 * c4 + 1) * 72 + n]);
            bq[j][1] = packhh(Btq[(2 * c4 + 8) * 72 + n], Btq[(2 * c4 + 9) * 72 + n]);
            bp[j][0] = packh2(__half2float(Btp[(2 * c4) * 72 + n]) * c0v,
                              __half2float(Btp[(2 * c4 + 1) * 72 + n]) * c1v);
            bp[j][1] = packh2(__half2float(Btp[(2 * c4 + 8) * 72 + n]) * c8v,
                              __half2float(Btp[(2 * c4 + 9) * 72 + n]) * c9v);
        }
#pragma unroll
        for (int i = 0; i < 2; i++)
#pragma unroll
            for (int j = 0; j < 4; j++) {
                mma16816f(accP[i][j], aE[i], bq[j]);
                mma16816f(accQ[i][j], aE[i], bp[j]);
            }
        __syncthreads();
    }

    // Epilogue: both outputs
#pragma unroll
    for (int i = 0; i < 2; i++)
#pragma unroll
        for (int half = 0; half < 2; half++) {
            int gi = m0 + wm + i * 16 + r4 + half * 8;
            float rs = g_rinv[b * LL + gi];
            size_t base = ((size_t)b * LL + gi) * DD;
#pragma unroll
            for (int j = 0; j < 4; j++) {
                int col = n0 + wn + j * 8 + c4 * 2;
                float2 vp, vq;
                vp.x = accP[i][j][half * 2 + 0] * rs;
                vp.y = accP[i][j][half * 2 + 1] * rs;
                vq.x = accQ[i][j][half * 2 + 0];
                vq.y = accQ[i][j][half * 2 + 1];
                *(float2*)(OutP + base + col) = vp;
                *(float2*)(OutQ + base + col) = vq;
            }
        }
}

// ---------------------------------------------------------------------------
extern "C" void kernel_launch(void* const* d_in, const int* in_sizes, int n_in,
                              void* d_out, int out_size) {
    const float* p = (const float*)d_in[0];
    const float* q = (const float*)d_in[1];
    float* out = (float*)d_out;
    float* out_p = out;
    float* out_q = out + (size_t)BB * LL * DD;

    zero_sums<<<(BB * LL) / 256, 256>>>();
    normsplit_kernel<<<(2 * BB * LL) / 8, 256>>>(p, q);

    att_hmma_kernel<<<dim3(LL / 64, LL / 128, BB), 256>>>();

    inv_sums<<<(BB * LL) / 256, 256>>>();

    out_fused_kernel<<<dim3(DD / 64, LL / 128, BB), 256>>>(out_p, out_q);
}

// round 15
// speedup vs baseline: 2.1873x; 1.0961x over previous
#include <cuda_runtime.h>
#include <cuda_fp16.h>
#include <cstdint>
#include <math.h>

#define BB 64
#define LL 512
#define DD 768

// ---------------------------------------------------------------------------
// Scratch (device globals)
// ---------------------------------------------------------------------------
__device__ __half g_ph[(size_t)BB * LL * DD];   // normalized p, fp16
__device__ __half g_qh[(size_t)BB * LL * DD];   // normalized q, fp16
__device__ __half g_pf[(size_t)BB * LL * DD];   // raw p, fp16
__device__ __half g_qf[(size_t)BB * LL * DD];   // raw q, fp16
__device__ __half g_Ef[(size_t)BB * LL * LL];   // exp(att), fp16
__device__ float g_rsum[BB * LL];
__device__ float g_csum[BB * LL];
__device__ float g_rinv[BB * LL];
__device__ float g_cinv[BB * LL];

// ---------------------------------------------------------------------------
// Helpers
// ---------------------------------------------------------------------------
__device__ __forceinline__ uint32_t smem_u32(const void* p) {
    uint32_t a;
    asm("{ .reg .u64 t; cvta.to.shared.u64 t, %1; cvt.u32.u64 %0, t; }"
        : "=r"(a) : "l"(p));
    return a;
}
#define CP_ASYNC(dst, src) \
    asm volatile("cp.async.cg.shared.global [%0], [%1], 16;" :: "r"(dst), "l"(src))
#define CP_COMMIT() asm volatile("cp.async.commit_group;")
#define CP_WAIT1()  asm volatile("cp.async.wait_group 1;")
#define CP_WAIT0()  asm volatile("cp.async.wait_group 0;")

__device__ __forceinline__ void mma16816f(float* c, const uint32_t* a, const uint32_t* b) {
    asm volatile("mma.sync.aligned.m16n8k16.row.col.f32.f16.f16.f32 "
                 "{%0,%1,%2,%3}, {%4,%5,%6,%7}, {%8,%9}, {%0,%1,%2,%3};"
                 : "+f"(c[0]), "+f"(c[1]), "+f"(c[2]), "+f"(c[3])
                 : "r"(a[0]), "r"(a[1]), "r"(a[2]), "r"(a[3]), "r"(b[0]), "r"(b[1]));
}
__device__ __forceinline__ uint32_t packh2(float x, float y) {
    __half2 h = __floats2half2_rn(x, y);
    return *(uint32_t*)&h;
}
__device__ __forceinline__ uint32_t packhh(__half a, __half b) {
    __half2 h = __halves2half2(a, b);
    return *(uint32_t*)&h;
}

// ---------------------------------------------------------------------------
// zero the atomic accumulators / invert them
// ---------------------------------------------------------------------------
__global__ void zero_sums() {
    int i = blockIdx.x * blockDim.x + threadIdx.x;
    g_rsum[i] = 0.f;
    g_csum[i] = 0.f;
}
__global__ void inv_sums() {
    int i = blockIdx.x * blockDim.x + threadIdx.x;
    g_rinv[i] = 1.f / g_rsum[i];
    g_cinv[i] = 1.f / g_csum[i];
}

// ---------------------------------------------------------------------------
// Fused: L2-normalize rows -> fp16 normalized + fp16 raw copies. 1 warp/row.
// ---------------------------------------------------------------------------
__global__ void normsplit_kernel(const float* __restrict__ p,
                                 const float* __restrict__ q) {
    int warp = (blockIdx.x * blockDim.x + threadIdx.x) >> 5;
    int lane = threadIdx.x & 31;
    if (warp >= 2 * BB * LL) return;
    const float* src; __half *dstn, *dstr; int r;
    if (warp < BB * LL) { src = p; dstn = g_ph; dstr = g_pf; r = warp; }
    else                { src = q; dstn = g_qh; dstr = g_qf; r = warp - BB * LL; }
    const float4* row = (const float4*)(src + (size_t)r * DD);
    float4 v[6];
    float s = 0.f;
#pragma unroll
    for (int i = 0; i < 6; i++) {
        v[i] = row[lane + i * 32];
        s += v[i].x * v[i].x + v[i].y * v[i].y + v[i].z * v[i].z + v[i].w * v[i].w;
    }
#pragma unroll
    for (int o = 16; o; o >>= 1) s += __shfl_xor_sync(0xffffffffu, s, o);
    float inv = 1.f / fmaxf(sqrtf(s), 1e-8f);
    size_t base = (size_t)r * DD;
#pragma unroll
    for (int i = 0; i < 6; i++) {
        size_t e = base + 4 * (lane + i * 32);
        uint2 hn = make_uint2(packh2(v[i].x * inv, v[i].y * inv),
                              packh2(v[i].z * inv, v[i].w * inv));
        uint2 hr = make_uint2(packh2(v[i].x, v[i].y),
                              packh2(v[i].z, v[i].w));
        *(uint2*)(dstn + e) = hn;
        *(uint2*)(dstr + e) = hr;
    }
}

// ---------------------------------------------------------------------------
// HMMA att (fp16): E = exp(phat . qhat^T)
// BM=128, BN=128, BK=32, 2-stage cp.async. 8 warps as 2(m) x 4(n),
// warp tile 64x32, 32 MMAs per warp-iteration between syncs.
// Stage: A 128 x 80B = 10240, B 128 x 80B = 10240 -> 20480/stage, 2 = 40960.
// Epilogue: exp -> fp16 store + row/col atomics from the ROUNDED values.
// ---------------------------------------------------------------------------
#define ATT_STG 20480
#define ATT_BOFF 10240

__global__ __launch_bounds__(256, 2)
void att_hmma_kernel() {
    __shared__ __align__(128) char smc[2 * ATT_STG];

    int b = blockIdx.z;
    int m0 = blockIdx.y * 128, n0 = blockIdx.x * 128;
    const __half* Ph = g_ph + (size_t)b * LL * DD;
    const __half* Qh = g_qh + (size_t)b * LL * DD;

    uint32_t sb = smem_u32(smc);
    int t = threadIdx.x, wid = t >> 5, lane = t & 31;
    int wm = (wid >> 2) * 64, wn = (wid & 3) * 32;
    int r4 = lane >> 2, c4 = lane & 3;

    float acc[4][4][4];
#pragma unroll
    for (int i = 0; i < 4; i++)
#pragma unroll
        for (int j = 0; j < 4; j++)
#pragma unroll
            for (int k = 0; k < 4; k++) acc[i][j][k] = 0.f;

    // A: 128 rows x 4 chunks = 512 -> 2/thread. B: same -> 2/thread.
    auto LOAD = [&](int st, int k0) {
        uint32_t base = sb + (uint32_t)st * ATT_STG;
#pragma unroll
        for (int u = 0; u < 2; u++) {
            int c = t * 2 + u, row = c >> 2, cc = c & 3;
            CP_ASYNC(base + row * 80 + cc * 16,
                     Ph + (size_t)(m0 + row) * DD + k0 + cc * 8);
            CP_ASYNC(base + ATT_BOFF + row * 80 + cc * 16,
                     Qh + (size_t)(n0 + row) * DD + k0 + cc * 8);
        }
    };

    LOAD(0, 0);
    CP_COMMIT();

    const int NIT = DD / 32;   // 24
    for (int it = 0; it < NIT; it++) {
        if (it + 1 < NIT) { LOAD((it + 1) & 1, (it + 1) * 32); CP_COMMIT(); CP_WAIT1(); }
        else              { CP_WAIT0(); }
        __syncthreads();

        const uint32_t* At = (const uint32_t*)(smc + (it & 1) * ATT_STG);  // pitch 20 words
        const uint32_t* Bt = At + 2560;                                    // +10240 B

#pragma unroll
        for (int s = 0; s < 2; s++) {
            uint32_t aHi[4][4], bHi[4][2];
#pragma unroll
            for (int i = 0; i < 4; i++) {
                int r0 = (wm + i * 16 + r4) * 20;
                aHi[i][0] = At[r0 + 8 * s + c4];
                aHi[i][1] = At[r0 + 160 + 8 * s + c4];
                aHi[i][2] = At[r0 + 8 * s + c4 + 4];
                aHi[i][3] = At[r0 + 160 + 8 * s + c4 + 4];
            }
#pragma unroll
            for (int j = 0; j < 4; j++) {
                int n = (wn + j * 8 + r4) * 20;
                bHi[j][0] = Bt[n + 8 * s + c4];
                bHi[j][1] = Bt[n + 8 * s + c4 + 4];
            }
#pragma unroll
            for (int i = 0; i < 4; i++)
#pragma unroll
                for (int j = 0; j < 4; j++)
                    mma16816f(acc[i][j], aHi[i], bHi[j]);
        }
        __syncthreads();
    }

    // Epilogue: exp -> fp16 store; sums from the rounded values
#pragma unroll
    for (int i = 0; i < 4; i++)
#pragma unroll
        for (int half = 0; half < 2; half++) {
            int gi = m0 + wm + i * 16 + r4 + half * 8;
            size_t base = ((size_t)b * LL + gi) * LL;
#pragma unroll
            for (int j = 0; j < 4; j++) {
                int col = n0 + wn + j * 8 + c4 * 2;
                __half2 h = __floats2half2_rn(__expf(acc[i][j][half * 2 + 0]),
                                              __expf(acc[i][j][half * 2 + 1]));
                *(uint32_t*)(g_Ef + base + col) = *(uint32_t*)&h;
                float2 hv = __half22float2(h);
                acc[i][j][half * 2 + 0] = hv.x;
                acc[i][j][half * 2 + 1] = hv.y;
            }
        }

    // Row partial sums
#pragma unroll
    for (int i = 0; i < 4; i++)
#pragma unroll
        for (int half = 0; half < 2; half++) {
            float s = 0.f;
#pragma unroll
            for (int j = 0; j < 4; j++)
                s += acc[i][j][half * 2 + 0] + acc[i][j][half * 2 + 1];
            s += __shfl_xor_sync(0xffffffffu, s, 1);
            s += __shfl_xor_sync(0xffffffffu, s, 2);
            if (c4 == 0) {
                int gi = m0 + wm + i * 16 + r4 + half * 8;
                atomicAdd(&g_rsum[b * LL + gi], s);
            }
        }

    // Col partial sums (sum over the warp's 64 rows, then r4 reduction)
#pragma unroll
    for (int j = 0; j < 4; j++)
#pragma unroll
        for (int z = 0; z < 2; z++) {
            float s = 0.f;
#pragma unroll
            for (int i = 0; i < 4; i++)
                s += acc[i][j][z] + acc[i][j][2 + z];
            s += __shfl_xor_sync(0xffffffffu, s, 4);
            s += __shfl_xor_sync(0xffffffffu, s, 8);
            s += __shfl_xor_sync(0xffffffffu, s, 16);
            if (r4 == 0)
                atomicAdd(&g_csum[b * LL + n0 + wn + j * 8 + c4 * 2 + z], s);
        }
}

// ---------------------------------------------------------------------------
// FUSED output GEMMs (fp16): BK 16->32, 2-stage; 32 MMAs per warp-iter.
//   out_p[m,n] = rinv[m] * sum_k E[m,k] * q[k,n]
//   out_q[m,n] = sum_k (E[m,k]*cinv[k]) * p[k,n]
// Stage: E 128x80B = 10240, Bq 32x144B = 4608 @10240, Bp @14848 -> 19456.
// 2 stages = 38912; cinv 2x128B @38912. Total 39168 B static smem.
// ---------------------------------------------------------------------------
#define FO_BQ 10240
#define FO_BP 14848
#define FO_STG 19456
#define FO_CINV 38912

__global__ __launch_bounds__(256)
void out_fused_kernel(float* __restrict__ OutP, float* __restrict__ OutQ) {
    __shared__ __align__(128) char smc[39168];

    int b = blockIdx.z;
    int m0 = blockIdx.y * 128, n0 = blockIdx.x * 64;
    const __half* Ef = g_Ef + (size_t)b * LL * LL;
    const __half* Qb = g_qf + (size_t)b * LL * DD;
    const __half* Pb = g_pf + (size_t)b * LL * DD;
    const float* cv = g_cinv + b * LL;

    uint32_t sb = smem_u32(smc);
    int t = threadIdx.x, wid = t >> 5, lane = t & 31;
    int wm = (wid >> 1) * 32, wn = (wid & 1) * 32;
    int r4 = lane >> 2, c4 = lane & 3;

    float accP[2][4][4], accQ[2][4][4];
#pragma unroll
    for (int i = 0; i < 2; i++)
#pragma unroll
        for (int j = 0; j < 4; j++)
#pragma unroll
            for (int k = 0; k < 4; k++) { accP[i][j][k] = 0.f; accQ[i][j][k] = 0.f; }

    // E: 128 rows x 4 chunks = 512 -> 2/thread.
    // Bq: 32 rows x 8 chunks = 256 -> 1/thread. Bp: same. cinv: t<8.
    int brow = t >> 3, bcc = t & 7;
    auto LOAD = [&](int st, int k0) {
        uint32_t base = sb + (uint32_t)st * FO_STG;
#pragma unroll
        for (int u = 0; u < 2; u++) {
            int c = t * 2 + u, row = c >> 2, cc = c & 3;
            CP_ASYNC(base + row * 80 + cc * 16,
                     Ef + (size_t)(m0 + row) * LL + k0 + cc * 8);
        }
        CP_ASYNC(base + FO_BQ + brow * 144 + bcc * 16,
                 Qb + (size_t)(k0 + brow) * DD + n0 + bcc * 8);
        CP_ASYNC(base + FO_BP + brow * 144 + bcc * 16,
                 Pb + (size_t)(k0 + brow) * DD + n0 + bcc * 8);
        if (t < 8)
            CP_ASYNC(sb + FO_CINV + (uint32_t)st * 128 + t * 16, cv + k0 + t * 4);
    };

    LOAD(0, 0);
    CP_COMMIT();

    const int NIT = LL / 32;   // 16
    for (int it = 0; it < NIT; it++) {
        if (it + 1 < NIT) { LOAD((it + 1) & 1, (it + 1) * 32); CP_COMMIT(); CP_WAIT1(); }
        else              { CP_WAIT0(); }
        __syncthreads();

        const uint32_t* At = (const uint32_t*)(smc + (it & 1) * FO_STG);       // pitch 20 words
        const __half* Btq = (const __half*)(smc + (it & 1) * FO_STG + FO_BQ);  // [32][72]
        const __half* Btp = (const __half*)(smc + (it & 1) * FO_STG + FO_BP);  // [32][72]
        const float* Cs = (const float*)(smc + FO_CINV + (it & 1) * 128);      // [32]

#pragma unroll
        for (int s = 0; s < 2; s++) {
            int ks = 16 * s;
            float c0v = Cs[ks + 2 * c4],     c1v = Cs[ks + 2 * c4 + 1];
            float c8v = Cs[ks + 2 * c4 + 8], c9v = Cs[ks + 2 * c4 + 9];

            uint32_t aE[2][4];
#pragma unroll
            for (int i = 0; i < 2; i++) {
                int r0 = (wm + i * 16 + r4) * 20;
                aE[i][0] = At[r0 + 8 * s + c4];
                aE[i][1] = At[r0 + 160 + 8 * s + c4];
                aE[i][2] = At[r0 + 8 * s + c4 + 4];
                aE[i][3] = At[r0 + 160 + 8 * s + c4 + 4];
            }

            uint32_t bq[4][2], bp[4][2];
#pragma unroll
            for (int j = 0; j < 4; j++) {
                int n = wn + j * 8 + r4;
                bq[j][0] = packhh(Btq[(ks + 2 * c4) * 72 + n],
                                  Btq[(ks + 2 * c4 + 1) * 72 + n]);
                bq[j][1] = packhh(Btq[(ks + 2 * c4 + 8) * 72 + n],
                                  Btq[(ks + 2 * c4 + 9) * 72 + n]);
                bp[j][0] = packh2(__half2float(Btp[(ks + 2 * c4) * 72 + n]) * c0v,
                                  __half2float(Btp[(ks + 2 * c4 + 1) * 72 + n]) * c1v);
                bp[j][1] = packh2(__half2float(Btp[(ks + 2 * c4 + 8) * 72 + n]) * c8v,
                                  __half2float(Btp[(ks + 2 * c4 + 9) * 72 + n]) * c9v);
            }
#pragma unroll
            for (int i = 0; i < 2; i++)
#pragma unroll
                for (int j = 0; j < 4; j++) {
                    mma16816f(accP[i][j], aE[i], bq[j]);
                    mma16816f(accQ[i][j], aE[i], bp[j]);
                }
        }
        __syncthreads();
    }

    // Epilogue: both outputs
#pragma unroll
    for (int i = 0; i < 2; i++)
#pragma unroll
        for (int half = 0; half < 2; half++) {
            int gi = m0 + wm + i * 16 + r4 + half * 8;
            float rs = g_rinv[b * LL + gi];
            size_t base = ((size_t)b * LL + gi) * DD;
#pragma unroll
            for (int j = 0; j < 4; j++) {
                int col = n0 + wn + j * 8 + c4 * 2;
                float2 vp, vq;
                vp.x = accP[i][j][half * 2 + 0] * rs;
                vp.y = accP[i][j][half * 2 + 1] * rs;
                vq.x = accQ[i][j][half * 2 + 0];
                vq.y = accQ[i][j][half * 2 + 1];
                *(float2*)(OutP + base + col) = vp;
                *(float2*)(OutQ + base + col) = vq;
            }
        }
}

// ---------------------------------------------------------------------------
extern "C" void kernel_launch(void* const* d_in, const int* in_sizes, int n_in,
                              void* d_out, int out_size) {
    const float* p = (const float*)d_in[0];
    const float* q = (const float*)d_in[1];
    float* out = (float*)d_out;
    float* out_p = out;
    float* out_q = out + (size_t)BB * LL * DD;

    zero_sums<<<(BB * LL) / 256, 256>>>();
    normsplit_kernel<<<(2 * BB * LL) / 8, 256>>>(p, q);

    att_hmma_kernel<<<dim3(LL / 128, LL / 128, BB), 256>>>();

    inv_sums<<<(BB * LL) / 256, 256>>>();

    out_fused_kernel<<<dim3(DD / 64, LL / 128, BB), 256>>>(out_p, out_q);
}